// round 5
// baseline (speedup 1.0000x reference)
#include <cuda_runtime.h>
#include <cuda_bf16.h>
#include <cstdint>

#define NNODE 4096
#define FD 256
#define HD 256
#define KEXP 3
#define TSTEP 5
#define G4 1024
#define SIG_LO 10
#define SIG_HI 253   // F_DIM - END

#define NF  ((size_t)NNODE * FD)     // 1048576
#define NG4 ((size_t)NNODE * G4)

// ---------------- scratch (device globals: no allocation allowed) ----------------
__device__ float g_Af[KEXP][(size_t)NNODE * NNODE];   // a_bin + I, {0,1,2}
__device__ float g_dinv[KEXP][NNODE];
__device__ float g_y[KEXP][NF];
__device__ float g_xt[KEXP][NF];
__device__ float g_gx[KEXP][NG4];          // interleaved gate layout [n][4f+g]
__device__ float g_h[2][KEXP][NF];         // double-buffered hidden state
__device__ float g_c[KEXP][NF];
__device__ float g_delta[KEXP][NF];
__device__ float g_wih_p[KEXP][G4 * HD];   // gate-interleaved weights
__device__ float g_whh_p[KEXP][G4 * HD];
__device__ float g_b_p[KEXP][G4];          // b_ih + b_hh, interleaved

__device__ __forceinline__ float sigf(float v) { return 1.0f / (1.0f + expf(-v)); }

__device__ __forceinline__ void mma_tf32(float c[4], const uint32_t a[4], const uint32_t b[2]) {
    asm volatile(
        "mma.sync.aligned.m16n8k8.row.col.f32.tf32.tf32.f32 "
        "{%0,%1,%2,%3}, {%4,%5,%6,%7}, {%8,%9}, {%0,%1,%2,%3};"
        : "+f"(c[0]), "+f"(c[1]), "+f"(c[2]), "+f"(c[3])
        : "r"(a[0]), "r"(a[1]), "r"(a[2]), "r"(a[3]), "r"(b[0]), "r"(b[1]));
}

__device__ __forceinline__ void cp16(float* sdst, const float* gsrc) {
    uint32_t s = (uint32_t)__cvta_generic_to_shared(sdst);
    asm volatile("cp.async.cg.shared.global [%0], [%1], 16;\n" :: "r"(s), "l"(gsrc));
}
__device__ __forceinline__ void cp_commit() { asm volatile("cp.async.commit_group;\n"); }
template <int N>
__device__ __forceinline__ void cp_wait() { asm volatile("cp.async.wait_group %0;\n" :: "n"(N)); }

__device__ __forceinline__ uint32_t fbits(float f) { return __float_as_uint(f); }

// ---------------- prep: one coalesced pass over adj ----------------
__global__ void prep_kernel(const int* __restrict__ adj, float* __restrict__ out_adj) {
    const int i = blockIdx.x;
    const int tid = threadIdx.x;
    const int* row = adj + (size_t)i * NNODE * KEXP;
    float* orow = out_adj + (size_t)i * NNODE * KEXP;
    float* A0 = &g_Af[0][(size_t)i * NNODE];
    float* A1 = &g_Af[1][(size_t)i * NNODE];
    float* A2 = &g_Af[2][(size_t)i * NNODE];
    float s0 = 0.f, s1 = 0.f, s2 = 0.f;
    for (int j = tid; j < NNODE; j += 256) {
        int b = j * 3;
        int a0 = row[b + 0], a1 = row[b + 1], a2 = row[b + 2];
        float v0 = a0 ? 1.f : 0.f, v1 = a1 ? 1.f : 0.f, v2 = a2 ? 1.f : 0.f;
        if (j == i) { v0 += 1.f; v1 += 1.f; v2 += 1.f; }
        A0[j] = v0; A1[j] = v1; A2[j] = v2;
        orow[b + 0] = (float)a0; orow[b + 1] = (float)a1; orow[b + 2] = (float)a2;
        s0 += v0; s1 += v1; s2 += v2;
    }
    __shared__ float sh[3][256];
    sh[0][tid] = s0; sh[1][tid] = s1; sh[2][tid] = s2;
    __syncthreads();
    for (int off = 128; off > 0; off >>= 1) {
        if (tid < off) {
            sh[0][tid] += sh[0][tid + off];
            sh[1][tid] += sh[1][tid + off];
            sh[2][tid] += sh[2][tid + off];
        }
        __syncthreads();
    }
    if (tid < 3) g_dinv[tid][i] = rsqrtf(sh[tid][0]);
}

// ---------------- permute LSTM weights to interleaved gate layout ----------------
// out row j = 4*f + gate  <-  in row gate*256 + f  (torch order i,f,g,o)
__global__ void permute_w(const float* __restrict__ w_ih, const float* __restrict__ w_hh,
                          const float* __restrict__ b_ih, const float* __restrict__ b_hh) {
    int idx = blockIdx.x * 256 + threadIdx.x;     // < 3 * G4 * HD
    int k = idx / (G4 * HD);
    int rem = idx - k * (G4 * HD);
    int j = rem >> 8, h = rem & 255;
    int src = (j & 3) * 256 + (j >> 2);
    g_wih_p[k][j * 256 + h] = w_ih[(size_t)k * G4 * HD + src * 256 + h];
    g_whh_p[k][j * 256 + h] = w_hh[(size_t)k * G4 * HD + src * 256 + h];
    if (h == 0) g_b_p[k][j] = b_ih[k * G4 + src] + b_hh[k * G4 + src];
}

// ---------------- TF32 tensor-core GEMM, cp.async double-buffered, z-batched ----------------
// C[M,Nn] = A[M,Kd] @ op(B); block tile 128x128x32, 256 thr = 8 warps (2x4), warp tile 64x32.
// EPI=0: plain (+rowscale +bias). EPI=1: fused LSTM gate (interleaved layout).
// EPI=2: fused fc (tanh -> delta, zbar).
#define APAD 44
#define BPAD 136

template <int TRANSB, int EPI>
__global__ void __launch_bounds__(256, 2) mma_gemm(
    const float* __restrict__ A, size_t sA,
    const float* __restrict__ B, size_t sB,
    const float* __restrict__ rowscale,
    const float* __restrict__ bias, int sBias,
    float* __restrict__ C, size_t sC,
    const float* __restrict__ gx,     // EPI=1 (base, z-strided NG4)
    float* __restrict__ cbuf,         // EPI=1 (z-strided NF)
    float* __restrict__ hout,         // EPI=1 (z-strided NF)
    const float* __restrict__ x,      // EPI=2 (shared)
    float* __restrict__ delta,        // EPI=2 (z-strided NF)
    float* __restrict__ zbar,         // EPI=2 (shared, K-strided writes)
    int Nn, int Kd) {

    constexpr int AS_STAGE = 128 * APAD;
    constexpr int BS_STAGE = TRANSB ? (128 * APAD) : (32 * BPAD);

    extern __shared__ float smem[];
    float* As = smem;
    float* Bs = smem + 2 * AS_STAGE;

    const int z = blockIdx.z;
    A += (size_t)z * sA;
    B += (size_t)z * sB;
    if (EPI == 0 && C) C += (size_t)z * sC;
    if (rowscale) rowscale += z * NNODE;
    if (bias) bias += z * sBias;
    if (EPI == 1) { gx += (size_t)z * NG4; cbuf += (size_t)z * NF; hout += (size_t)z * NF; }
    if (EPI == 2) { delta += (size_t)z * NF; }

    const int tid = threadIdx.x;
    const int wid = tid >> 5, lane = tid & 31;
    const int warp_m = wid >> 2;
    const int warp_n = wid & 3;
    const int g = lane >> 2, c4 = lane & 3;
    const int bm = blockIdx.y * 128, bn = blockIdx.x * 128;

    const int nIter = Kd >> 5;

    auto issue = [&](int p, int it) {
        const int k0 = it << 5;
        #pragma unroll
        for (int q = 0; q < 4; q++) {
            int id = tid + 256 * q;
            int m = id >> 3, c = id & 7;
            cp16(As + p * AS_STAGE + m * APAD + c * 4,
                 A + (size_t)(bm + m) * Kd + k0 + c * 4);
        }
        if (TRANSB) {
            #pragma unroll
            for (int q = 0; q < 4; q++) {
                int id = tid + 256 * q;
                int n = id >> 3, c = id & 7;
                cp16(Bs + p * BS_STAGE + n * APAD + c * 4,
                     B + (size_t)(bn + n) * Kd + k0 + c * 4);
            }
        } else {
            #pragma unroll
            for (int q = 0; q < 4; q++) {
                int id = tid + 256 * q;
                int kr = id >> 5, c = id & 31;
                cp16(Bs + p * BS_STAGE + kr * BPAD + c * 4,
                     B + (size_t)(k0 + kr) * Nn + bn + c * 4);
            }
        }
    };

    float acc[4][4][4] = {};

    issue(0, 0); cp_commit();
    issue(1, 1); cp_commit();

    for (int i = 0; i < nIter; i++) {
        const int p = i & 1;
        cp_wait<1>();
        __syncthreads();

        const float* Ab = As + p * AS_STAGE;
        const float* Bb = Bs + p * BS_STAGE;
        #pragma unroll
        for (int ks = 0; ks < 4; ks++) {
            const int kb = ks * 8;
            uint32_t af[4][4], bf[4][2];
            #pragma unroll
            for (int mt = 0; mt < 4; mt++) {
                const float* pa = Ab + (warp_m * 64 + mt * 16 + g) * APAD + kb + c4;
                af[mt][0] = fbits(pa[0]);
                af[mt][1] = fbits(pa[8 * APAD]);
                af[mt][2] = fbits(pa[4]);
                af[mt][3] = fbits(pa[8 * APAD + 4]);
            }
            #pragma unroll
            for (int nt = 0; nt < 4; nt++) {
                if (TRANSB) {
                    const float* pb = Bb + (warp_n * 32 + nt * 8 + g) * APAD + kb + c4;
                    bf[nt][0] = fbits(pb[0]);
                    bf[nt][1] = fbits(pb[4]);
                } else {
                    const float* pb = Bb + (kb + c4) * BPAD + warp_n * 32 + nt * 8 + g;
                    bf[nt][0] = fbits(pb[0]);
                    bf[nt][1] = fbits(pb[4 * BPAD]);
                }
            }
            #pragma unroll
            for (int mt = 0; mt < 4; mt++)
                #pragma unroll
                for (int nt = 0; nt < 4; nt++)
                    mma_tf32(acc[mt][nt], af[mt], bf[nt]);
        }
        __syncthreads();
        if (i + 2 < nIter) issue(p, i + 2);
        cp_commit();
    }

    // ---- epilogue ----
    #pragma unroll
    for (int mt = 0; mt < 4; mt++) {
        #pragma unroll
        for (int nt = 0; nt < 4; nt++) {
            const int col = bn + warp_n * 32 + nt * 8 + c4 * 2;
            #pragma unroll
            for (int rr = 0; rr < 2; rr++) {
                const int row = bm + warp_m * 64 + mt * 16 + g + rr * 8;
                float v0 = acc[mt][nt][rr * 2 + 0];
                float v1 = acc[mt][nt][rr * 2 + 1];
                if (EPI == 0) {
                    if (rowscale) { float s = rowscale[row]; v0 *= s; v1 *= s; }
                    if (bias) { v0 += bias[col]; v1 += bias[col + 1]; }
                    *(float2*)(C + (size_t)row * Nn + col) = make_float2(v0, v1);
                } else if (EPI == 1) {
                    // interleaved gates: cols 4f..4f+3 = (i,f,g,o) of feature f
                    float2 gv = *(const float2*)(gx + (size_t)row * G4 + col);
                    float s0 = v0 + gv.x, s1 = v1 + gv.y;
                    float o0 = __shfl_xor_sync(0xffffffffu, s0, 1);
                    float o1 = __shfl_xor_sync(0xffffffffu, s1, 1);
                    if ((c4 & 1) == 0) {
                        // this thread holds (i, f); partner gave (g, o)
                        int f = col >> 2;
                        size_t ix = (size_t)row * HD + f;
                        float cp = cbuf[ix];
                        float cn = sigf(s1) * cp + sigf(s0) * tanhf(o0);
                        cbuf[ix] = cn;
                        hout[ix] = sigf(o1) * tanhf(cn);
                    }
                } else {  // EPI == 2
                    v0 += bias[col]; v1 += bias[col + 1];
                    float d0 = tanhf(v0), d1 = tanhf(v1);
                    size_t ix = (size_t)row * FD + col;
                    delta[ix] = d0; delta[ix + 1] = d1;
                    float z0 = x[ix] + d0, z1 = x[ix + 1] + d1;
                    if (col >= SIG_LO && col < SIG_HI) z0 = sigf(z0);
                    if (col + 1 >= SIG_LO && col + 1 < SIG_HI) z1 = sigf(z1);
                    zbar[ix * KEXP + z] = z0;
                    zbar[(ix + 1) * KEXP + z] = z1;
                }
            }
        }
    }
}

// ---------------- t=0 LSTM init (h=c=0): pure function of gx ----------------
__global__ void lstm_init() {
    size_t idx = (size_t)blockIdx.x * 256 + threadIdx.x;   // < 3 * NNODE * HD
    int z = (int)(idx >> 20);
    size_t r = idx & (NF - 1);
    float4 gv = *(const float4*)(&g_gx[z][r * 4]);   // (i, f, g, o) adjacent
    float cn = sigf(gv.x) * tanhf(gv.z);
    g_c[z][r] = cn;
    g_h[0][z][r] = sigf(gv.w) * tanhf(cn);
}

// ---------------- final prediction ----------------
__global__ void final_pred(const float* __restrict__ x, float* __restrict__ out_pred) {
    int idx = blockIdx.x * 256 + threadIdx.x;
    int f = idx & 255;
    float d = (g_delta[0][idx] + g_delta[1][idx] + g_delta[2][idx]) * (1.0f / 3.0f);
    float z = x[idx] + d;
    if (f >= SIG_LO && f < SIG_HI) z = sigf(z);
    out_pred[idx] = z;
}

// ---------------- launcher ----------------
extern "C" void kernel_launch(void* const* d_in, const int* in_sizes, int n_in,
                              void* d_out, int out_size) {
    const float* x     = (const float*)d_in[0];
    const float* gnn_w = (const float*)d_in[1];
    const float* gnn_b = (const float*)d_in[2];
    const float* w_ih  = (const float*)d_in[3];
    const float* w_hh  = (const float*)d_in[4];
    const float* b_ih  = (const float*)d_in[5];
    const float* b_hh  = (const float*)d_in[6];
    const float* fc_w  = (const float*)d_in[7];
    const float* fc_b  = (const float*)d_in[8];
    const int*   adj   = (const int*)d_in[9];

    float* out = (float*)d_out;
    float* out_pred = out;
    float* out_zbar = out + NF;
    float* out_adj  = out + NF * 4;

    float *p_Af, *p_dinv, *p_y, *p_xt, *p_gx, *p_h0, *p_h1, *p_c, *p_delta, *p_wih, *p_whh, *p_bp;
    cudaGetSymbolAddress((void**)&p_Af,    g_Af);
    cudaGetSymbolAddress((void**)&p_dinv,  g_dinv);
    cudaGetSymbolAddress((void**)&p_y,     g_y);
    cudaGetSymbolAddress((void**)&p_xt,    g_xt);
    cudaGetSymbolAddress((void**)&p_gx,    g_gx);
    cudaGetSymbolAddress((void**)&p_h0,    g_h);           // g_h[0]
    p_h1 = p_h0 + KEXP * NF;                               // g_h[1]
    cudaGetSymbolAddress((void**)&p_c,     g_c);
    cudaGetSymbolAddress((void**)&p_delta, g_delta);
    cudaGetSymbolAddress((void**)&p_wih,   g_wih_p);
    cudaGetSymbolAddress((void**)&p_whh,   g_whh_p);
    cudaGetSymbolAddress((void**)&p_bp,    g_b_p);

    const int smem_nn = (2 * 128 * APAD + 2 * 32 * BPAD) * 4;    // 79872
    const int smem_nt = (4 * 128 * APAD) * 4;                    // 90112
    cudaFuncSetAttribute(mma_gemm<0, 0>, cudaFuncAttributeMaxDynamicSharedMemorySize, smem_nn);
    cudaFuncSetAttribute(mma_gemm<1, 0>, cudaFuncAttributeMaxDynamicSharedMemorySize, smem_nt);
    cudaFuncSetAttribute(mma_gemm<1, 1>, cudaFuncAttributeMaxDynamicSharedMemorySize, smem_nt);
    cudaFuncSetAttribute(mma_gemm<1, 2>, cudaFuncAttributeMaxDynamicSharedMemorySize, smem_nt);

    prep_kernel<<<NNODE, 256>>>(adj, out_adj);
    permute_w<<<(KEXP * G4 * HD) / 256, 256>>>(w_ih, w_hh, b_ih, b_hh);

    const dim3 blk(256);

    // y = dinv * (x @ gnn_w)            [NN 4096x256x256, z=3]
    mma_gemm<0, 0><<<dim3(2, 32, 3), blk, smem_nn>>>(
        x, 0, gnn_w, (size_t)FD * HD, p_dinv, nullptr, 0,
        p_y, NF, nullptr, nullptr, nullptr, nullptr, nullptr, nullptr, HD, FD);

    // xt = dinv * (A @ y) + gnn_b       [NN 4096x256x4096, z=3]
    mma_gemm<0, 0><<<dim3(2, 32, 3), blk, smem_nn>>>(
        p_Af, (size_t)NNODE * NNODE, p_y, NF, p_dinv, gnn_b, HD,
        p_xt, NF, nullptr, nullptr, nullptr, nullptr, nullptr, nullptr, HD, NNODE);

    // gx = xt @ wih_p^T + b_p           [NT 4096x1024x256, z=3] (interleaved gates)
    mma_gemm<1, 0><<<dim3(8, 32, 3), blk, smem_nt>>>(
        p_xt, NF, p_wih, (size_t)G4 * HD, nullptr, p_bp, G4,
        p_gx, NG4, nullptr, nullptr, nullptr, nullptr, nullptr, nullptr, G4, HD);

    // t = 0
    lstm_init<<<(int)((KEXP * NF) / 256), 256>>>();

    // t = 1..4 : fused GEMM + gate
    float* hbuf[2] = { p_h0, p_h1 };
    for (int t = 1; t < TSTEP; t++) {
        float* hin  = hbuf[(t - 1) & 1];
        float* hout = hbuf[t & 1];
        mma_gemm<1, 1><<<dim3(8, 32, 3), blk, smem_nt>>>(
            hin, NF, p_whh, (size_t)G4 * HD, nullptr, nullptr, 0,
            nullptr, 0, p_gx, p_c, hout, nullptr, nullptr, nullptr, G4, HD);
    }

    // fc: delta = tanh(h @ fc_w^T + fc_b); zbar fused   [NT 4096x256x256, z=3]
    mma_gemm<1, 2><<<dim3(2, 32, 3), blk, smem_nt>>>(
        hbuf[(TSTEP - 1) & 1], NF, fc_w, (size_t)FD * HD, nullptr, fc_b, FD,
        nullptr, 0, nullptr, nullptr, nullptr, x, p_delta, out_zbar, FD, HD);

    final_pred<<<(int)(NF / 256), 256>>>(x, out_pred);
}

// round 6
// speedup vs baseline: 1.3878x; 1.3878x over previous
#include <cuda_runtime.h>
#include <cuda_fp16.h>
#include <cstdint>

#define NNODE 4096
#define FD 256
#define HD 256
#define KEXP 3
#define TSTEP 5
#define G4 1024
#define SIG_LO 10
#define SIG_HI 253   // F_DIM - END

#define NF  ((size_t)NNODE * FD)     // 1048576
#define NG4 ((size_t)NNODE * G4)

// ---------------- scratch (device globals: no allocation allowed) ----------------
__device__ __half g_Ah[KEXP][(size_t)NNODE * NNODE];  // a_bin + I, {0,1,2} exact
__device__ float  g_dinv[KEXP][NNODE];
__device__ __half g_yT[KEXP][(size_t)HD * NNODE];     // (dinv_j * x@w)^T  [h][n]
__device__ __half g_xt[KEXP][NF];                     // gnn_out, half, row-major
__device__ float  g_gx[KEXP][NG4];                    // interleaved gates [n][4f+g]
__device__ __half g_h[2][KEXP][NF];                   // double-buffered hidden
__device__ float  g_c[KEXP][NF];
__device__ float  g_delta[KEXP][NF];
__device__ __half g_wih_p[KEXP][G4 * HD];             // gate-interleaved, half
__device__ __half g_whh_p[KEXP][G4 * HD];
__device__ float  g_b_p[KEXP][G4];                    // b_ih + b_hh interleaved
__device__ __half g_wT[KEXP][FD * HD];                // gnn_w transposed [h][f]
__device__ __half g_fcw[KEXP][FD * HD];               // fc_w cast (already [n][k])
__device__ __half g_xh[NF];                           // x cast

__device__ __forceinline__ float sigf(float v) { return 1.0f / (1.0f + expf(-v)); }

__device__ __forceinline__ void mma_f16(float c[4], const uint32_t a[4], const uint32_t b[2]) {
    asm volatile(
        "mma.sync.aligned.m16n8k16.row.col.f32.f16.f16.f32 "
        "{%0,%1,%2,%3}, {%4,%5,%6,%7}, {%8,%9}, {%0,%1,%2,%3};"
        : "+f"(c[0]), "+f"(c[1]), "+f"(c[2]), "+f"(c[3])
        : "r"(a[0]), "r"(a[1]), "r"(a[2]), "r"(a[3]), "r"(b[0]), "r"(b[1]));
}

__device__ __forceinline__ void cp16(void* sdst, const void* gsrc) {
    uint32_t s = (uint32_t)__cvta_generic_to_shared(sdst);
    asm volatile("cp.async.cg.shared.global [%0], [%1], 16;\n" :: "r"(s), "l"(gsrc));
}
__device__ __forceinline__ void cp_commit() { asm volatile("cp.async.commit_group;\n"); }
template <int N>
__device__ __forceinline__ void cp_wait() { asm volatile("cp.async.wait_group %0;\n" :: "n"(N)); }

__device__ __forceinline__ uint32_t lds32(const __half* p) { return *(const uint32_t*)p; }

// ---------------- prep: one vectorized pass over adj ----------------
__global__ void prep_kernel(const int* __restrict__ adj, float* __restrict__ out_adj) {
    const int i = blockIdx.x;
    const int tid = threadIdx.x;
    const int* row = adj + (size_t)i * NNODE * KEXP;
    float* orow = out_adj + (size_t)i * NNODE * KEXP;
    __half* A0 = &g_Ah[0][(size_t)i * NNODE];
    __half* A1 = &g_Ah[1][(size_t)i * NNODE];
    __half* A2 = &g_Ah[2][(size_t)i * NNODE];
    float s0 = 0.f, s1 = 0.f, s2 = 0.f;
    for (int j4 = tid * 4; j4 < NNODE; j4 += 1024) {
        int4 w0 = *(const int4*)(row + j4 * 3);
        int4 w1 = *(const int4*)(row + j4 * 3 + 4);
        int4 w2 = *(const int4*)(row + j4 * 3 + 8);
        int a[4][3] = {{w0.x, w0.y, w0.z}, {w0.w, w1.x, w1.y},
                       {w1.z, w1.w, w2.x}, {w2.y, w2.z, w2.w}};
        float v[4][3];
        #pragma unroll
        for (int e = 0; e < 4; e++) {
            int j = j4 + e;
            #pragma unroll
            for (int c = 0; c < 3; c++) {
                float val = a[e][c] ? 1.f : 0.f;
                if (j == i) val += 1.f;
                v[e][c] = val;
            }
            s0 += v[e][0]; s1 += v[e][1]; s2 += v[e][2];
        }
        float4 o0 = make_float4((float)a[0][0], (float)a[0][1], (float)a[0][2], (float)a[1][0]);
        float4 o1 = make_float4((float)a[1][1], (float)a[1][2], (float)a[2][0], (float)a[2][1]);
        float4 o2 = make_float4((float)a[2][2], (float)a[3][0], (float)a[3][1], (float)a[3][2]);
        *(float4*)(orow + j4 * 3)     = o0;
        *(float4*)(orow + j4 * 3 + 4) = o1;
        *(float4*)(orow + j4 * 3 + 8) = o2;
        *(__half2*)(A0 + j4)     = __floats2half2_rn(v[0][0], v[1][0]);
        *(__half2*)(A0 + j4 + 2) = __floats2half2_rn(v[2][0], v[3][0]);
        *(__half2*)(A1 + j4)     = __floats2half2_rn(v[0][1], v[1][1]);
        *(__half2*)(A1 + j4 + 2) = __floats2half2_rn(v[2][1], v[3][1]);
        *(__half2*)(A2 + j4)     = __floats2half2_rn(v[0][2], v[1][2]);
        *(__half2*)(A2 + j4 + 2) = __floats2half2_rn(v[2][2], v[3][2]);
    }
    __shared__ float sh[3][256];
    sh[0][tid] = s0; sh[1][tid] = s1; sh[2][tid] = s2;
    __syncthreads();
    for (int off = 128; off > 0; off >>= 1) {
        if (tid < off) {
            sh[0][tid] += sh[0][tid + off];
            sh[1][tid] += sh[1][tid + off];
            sh[2][tid] += sh[2][tid + off];
        }
        __syncthreads();
    }
    if (tid < 3) g_dinv[tid][i] = rsqrtf(sh[tid][0]);
}

// ---------------- conversions ----------------
__global__ void conv_x(const float* __restrict__ x) {
    int idx = blockIdx.x * 256 + threadIdx.x;
    g_xh[idx] = __float2half(x[idx]);
}

// gnn_w transpose->half, fc_w cast->half
__global__ void conv_w(const float* __restrict__ gnn_w, const float* __restrict__ fc_w) {
    int idx = blockIdx.x * 256 + threadIdx.x;   // < KEXP*FD*HD
    int k = idx / (FD * HD);
    int rem = idx - k * (FD * HD);
    int f = rem / HD, h = rem % HD;
    g_wT[k][h * FD + f] = __float2half(gnn_w[idx]);
    g_fcw[k][rem] = __float2half(fc_w[idx]);
}

// permute LSTM weights to interleaved gate layout; half
__global__ void permute_w(const float* __restrict__ w_ih, const float* __restrict__ w_hh,
                          const float* __restrict__ b_ih, const float* __restrict__ b_hh) {
    int idx = blockIdx.x * 256 + threadIdx.x;   // < KEXP*G4*HD
    int k = idx / (G4 * HD);
    int rem = idx - k * (G4 * HD);
    int j = rem >> 8, h = rem & 255;
    int src = (j & 3) * 256 + (j >> 2);   // torch gate order i,f,g,o
    g_wih_p[k][j * 256 + h] = __float2half(w_ih[(size_t)k * G4 * HD + src * 256 + h]);
    g_whh_p[k][j * 256 + h] = __float2half(w_hh[(size_t)k * G4 * HD + src * 256 + h]);
    if (h == 0) g_b_p[k][j] = b_ih[k * G4 + src] + b_hh[k * G4 + src];
}

// ---------------- fp16 tensor-core GEMM (all NT), cp.async double-buffered ----------------
// C[M,Nn] = A[M,Kd] @ B[Nn,Kd]^T.  Block tile BM x 128 x 64, 256 thr = (2 x 4) warps.
// EPI: 0=fp32 out +bias | 1=LSTM gate | 2=fc fuse | 3=half out +rowscale+bias | 4=half transposed out +rowscale
#define AS_LD 72   // 64 + 8 halves

template <int BM, int EPI>
__global__ void __launch_bounds__(256, 2) mma_gemm(
    const __half* __restrict__ A, size_t sA,
    const __half* __restrict__ B, size_t sB,
    const float* __restrict__ rowscale,
    const float* __restrict__ bias, int sBias,
    void* __restrict__ Cv, size_t sC,
    const float* __restrict__ gx,     // EPI=1
    float* __restrict__ cbuf,         // EPI=1
    __half* __restrict__ hout,        // EPI=1
    const float* __restrict__ x,      // EPI=2
    float* __restrict__ delta,        // EPI=2
    float* __restrict__ zbar,         // EPI=2
    int Nn, int Kd) {

    constexpr int MT = BM / 32;
    constexpr int AS_STAGE = BM * AS_LD;
    constexpr int BS_STAGE = 128 * AS_LD;
    constexpr int ACH = BM / 32;      // A cp chunks per thread

    extern __shared__ __half smem[];
    __half* As = smem;
    __half* Bs = smem + 2 * AS_STAGE;

    const int z = blockIdx.z;
    A += (size_t)z * sA;
    B += (size_t)z * sB;
    float* Cf = (float*)Cv;
    __half* Ch = (__half*)Cv;
    if (EPI == 0) Cf += (size_t)z * sC;
    if (EPI == 3 || EPI == 4) Ch += (size_t)z * sC;
    if (rowscale) rowscale += z * NNODE;
    if (bias) bias += z * sBias;
    if (EPI == 1) { gx += (size_t)z * NG4; cbuf += (size_t)z * NF; hout += (size_t)z * NF; }
    if (EPI == 2) { delta += (size_t)z * NF; }

    const int tid = threadIdx.x;
    const int wid = tid >> 5, lane = tid & 31;
    const int warp_m = wid >> 2;
    const int warp_n = wid & 3;
    const int g = lane >> 2, c4 = lane & 3;
    const int bm = blockIdx.y * BM, bn = blockIdx.x * 128;

    const int nIter = Kd >> 6;

    auto issue = [&](int p, int it) {
        const int k0 = it << 6;
        #pragma unroll
        for (int q = 0; q < ACH; q++) {
            int id = tid + 256 * q;
            int m = id >> 3, c = id & 7;
            cp16(As + p * AS_STAGE + m * AS_LD + c * 8,
                 A + (size_t)(bm + m) * Kd + k0 + c * 8);
        }
        #pragma unroll
        for (int q = 0; q < 4; q++) {
            int id = tid + 256 * q;
            int n = id >> 3, c = id & 7;
            cp16(Bs + p * BS_STAGE + n * AS_LD + c * 8,
                 B + (size_t)(bn + n) * Kd + k0 + c * 8);
        }
    };

    float acc[MT][4][4] = {};

    issue(0, 0); cp_commit();
    issue(1, 1); cp_commit();

    for (int i = 0; i < nIter; i++) {
        const int p = i & 1;
        cp_wait<1>();
        __syncthreads();

        const __half* Ab = As + p * AS_STAGE;
        const __half* Bb = Bs + p * BS_STAGE;
        #pragma unroll
        for (int ks = 0; ks < 4; ks++) {
            const int kb = ks * 16;
            uint32_t af[MT][4], bf[4][2];
            #pragma unroll
            for (int mt = 0; mt < MT; mt++) {
                const __half* pa = Ab + (warp_m * (BM / 2) + mt * 16 + g) * AS_LD + kb + 2 * c4;
                af[mt][0] = lds32(pa);
                af[mt][1] = lds32(pa + 8 * AS_LD);
                af[mt][2] = lds32(pa + 8);
                af[mt][3] = lds32(pa + 8 * AS_LD + 8);
            }
            #pragma unroll
            for (int nt = 0; nt < 4; nt++) {
                const __half* pb = Bb + (warp_n * 32 + nt * 8 + g) * AS_LD + kb + 2 * c4;
                bf[nt][0] = lds32(pb);
                bf[nt][1] = lds32(pb + 8);
            }
            #pragma unroll
            for (int mt = 0; mt < MT; mt++)
                #pragma unroll
                for (int nt = 0; nt < 4; nt++)
                    mma_f16(acc[mt][nt], af[mt], bf[nt]);
        }
        __syncthreads();
        if (i + 2 < nIter) issue(p, i + 2);
        cp_commit();
    }

    // ---- epilogue ----
    #pragma unroll
    for (int mt = 0; mt < MT; mt++) {
        #pragma unroll
        for (int nt = 0; nt < 4; nt++) {
            const int col = bn + warp_n * 32 + nt * 8 + c4 * 2;
            #pragma unroll
            for (int rr = 0; rr < 2; rr++) {
                const int row = bm + warp_m * (BM / 2) + mt * 16 + g + rr * 8;
                float v0 = acc[mt][nt][rr * 2 + 0];
                float v1 = acc[mt][nt][rr * 2 + 1];
                if (EPI == 0) {
                    if (bias) { v0 += bias[col]; v1 += bias[col + 1]; }
                    *(float2*)(Cf + (size_t)row * Nn + col) = make_float2(v0, v1);
                } else if (EPI == 1) {
                    float2 gv = *(const float2*)(gx + (size_t)row * G4 + col);
                    float s0 = v0 + gv.x, s1 = v1 + gv.y;
                    float o0 = __shfl_xor_sync(0xffffffffu, s0, 1);
                    float o1 = __shfl_xor_sync(0xffffffffu, s1, 1);
                    if ((c4 & 1) == 0) {
                        int f = col >> 2;
                        size_t ix = (size_t)row * HD + f;
                        float cp = cbuf[ix];
                        float cn = sigf(s1) * cp + sigf(s0) * tanhf(o0);
                        cbuf[ix] = cn;
                        hout[ix] = __float2half(sigf(o1) * tanhf(cn));
                    }
                } else if (EPI == 2) {
                    v0 += bias[col]; v1 += bias[col + 1];
                    float d0 = tanhf(v0), d1 = tanhf(v1);
                    size_t ix = (size_t)row * FD + col;
                    delta[ix] = d0; delta[ix + 1] = d1;
                    float z0 = x[ix] + d0, z1 = x[ix + 1] + d1;
                    if (col >= SIG_LO && col < SIG_HI) z0 = sigf(z0);
                    if (col + 1 >= SIG_LO && col + 1 < SIG_HI) z1 = sigf(z1);
                    zbar[ix * KEXP + z] = z0;
                    zbar[(ix + 1) * KEXP + z] = z1;
                } else if (EPI == 3) {
                    float s = rowscale[row];
                    v0 = v0 * s + bias[col];
                    v1 = v1 * s + bias[col + 1];
                    *(__half2*)(Ch + (size_t)row * Nn + col) = __floats2half2_rn(v0, v1);
                } else {  // EPI == 4: transposed half out (+rowscale)
                    float s = rowscale[row];
                    Ch[(size_t)col * NNODE + row] = __float2half(v0 * s);
                    Ch[(size_t)(col + 1) * NNODE + row] = __float2half(v1 * s);
                }
            }
        }
    }
}

// ---------------- t=0 LSTM init (h=c=0) ----------------
__global__ void lstm_init() {
    size_t idx = (size_t)blockIdx.x * 256 + threadIdx.x;   // < KEXP*NF
    int z = (int)(idx >> 20);
    size_t r = idx & (NF - 1);
    float4 gv = *(const float4*)(&g_gx[z][r * 4]);   // (i, f, g, o)
    float cn = sigf(gv.x) * tanhf(gv.z);
    g_c[z][r] = cn;
    g_h[0][z][r] = __float2half(sigf(gv.w) * tanhf(cn));
}

// ---------------- final prediction ----------------
__global__ void final_pred(const float* __restrict__ x, float* __restrict__ out_pred) {
    int idx = blockIdx.x * 256 + threadIdx.x;
    int f = idx & 255;
    float d = (g_delta[0][idx] + g_delta[1][idx] + g_delta[2][idx]) * (1.0f / 3.0f);
    float z = x[idx] + d;
    if (f >= SIG_LO && f < SIG_HI) z = sigf(z);
    out_pred[idx] = z;
}

// ---------------- launcher ----------------
extern "C" void kernel_launch(void* const* d_in, const int* in_sizes, int n_in,
                              void* d_out, int out_size) {
    const float* x     = (const float*)d_in[0];
    const float* gnn_w = (const float*)d_in[1];
    const float* gnn_b = (const float*)d_in[2];
    const float* w_ih  = (const float*)d_in[3];
    const float* w_hh  = (const float*)d_in[4];
    const float* b_ih  = (const float*)d_in[5];
    const float* b_hh  = (const float*)d_in[6];
    const float* fc_w  = (const float*)d_in[7];
    const float* fc_b  = (const float*)d_in[8];
    const int*   adj   = (const int*)d_in[9];

    float* out = (float*)d_out;
    float* out_pred = out;
    float* out_zbar = out + NF;
    float* out_adj  = out + NF * 4;

    __half *p_Ah, *p_yT, *p_xt, *p_h0, *p_h1, *p_wih, *p_whh, *p_wT, *p_fcw, *p_xh;
    float *p_dinv, *p_gx, *p_c, *p_delta, *p_bp;
    cudaGetSymbolAddress((void**)&p_Ah,    g_Ah);
    cudaGetSymbolAddress((void**)&p_dinv,  g_dinv);
    cudaGetSymbolAddress((void**)&p_yT,    g_yT);
    cudaGetSymbolAddress((void**)&p_xt,    g_xt);
    cudaGetSymbolAddress((void**)&p_gx,    g_gx);
    cudaGetSymbolAddress((void**)&p_h0,    g_h);
    p_h1 = p_h0 + KEXP * NF;
    cudaGetSymbolAddress((void**)&p_c,     g_c);
    cudaGetSymbolAddress((void**)&p_delta, g_delta);
    cudaGetSymbolAddress((void**)&p_wih,   g_wih_p);
    cudaGetSymbolAddress((void**)&p_whh,   g_whh_p);
    cudaGetSymbolAddress((void**)&p_bp,    g_b_p);
    cudaGetSymbolAddress((void**)&p_wT,    g_wT);
    cudaGetSymbolAddress((void**)&p_fcw,   g_fcw);
    cudaGetSymbolAddress((void**)&p_xh,    g_xh);

    const int smem128 = (2 * 128 * AS_LD + 2 * 128 * AS_LD) * 2;   // 73728
    const int smem64  = (2 * 64 * AS_LD + 2 * 128 * AS_LD) * 2;    // 55296
    cudaFuncSetAttribute(mma_gemm<128, 0>, cudaFuncAttributeMaxDynamicSharedMemorySize, smem128);
    cudaFuncSetAttribute(mma_gemm<128, 1>, cudaFuncAttributeMaxDynamicSharedMemorySize, smem128);
    cudaFuncSetAttribute(mma_gemm<128, 2>, cudaFuncAttributeMaxDynamicSharedMemorySize, smem128);
    cudaFuncSetAttribute(mma_gemm<64, 3>,  cudaFuncAttributeMaxDynamicSharedMemorySize, smem64);
    cudaFuncSetAttribute(mma_gemm<128, 4>, cudaFuncAttributeMaxDynamicSharedMemorySize, smem128);

    prep_kernel<<<NNODE, 256>>>(adj, out_adj);
    conv_x<<<(int)(NF / 256), 256>>>(x);
    conv_w<<<(KEXP * FD * HD) / 256, 256>>>(gnn_w, fc_w);
    permute_w<<<(KEXP * G4 * HD) / 256, 256>>>(w_ih, w_hh, b_ih, b_hh);

    const dim3 blk(256);

    // yT = (dinv * (x @ gnn_w))^T       [NT 4096x256x256, z=3] -> half transposed
    mma_gemm<128, 4><<<dim3(2, 32, 3), blk, smem128>>>(
        p_xh, 0, p_wT, (size_t)FD * HD, p_dinv, nullptr, 0,
        p_yT, (size_t)HD * NNODE, nullptr, nullptr, nullptr, nullptr, nullptr, nullptr,
        HD, FD);

    // xt = dinv * (A @ y) + gnn_b       [NT 4096x256x4096, z=3] -> half row-major
    mma_gemm<64, 3><<<dim3(2, 64, 3), blk, smem64>>>(
        p_Ah, (size_t)NNODE * NNODE, p_yT, (size_t)HD * NNODE, p_dinv, gnn_b, HD,
        p_xt, NF, nullptr, nullptr, nullptr, nullptr, nullptr, nullptr, HD, NNODE);

    // gx = xt @ wih_p^T + b_p           [NT 4096x1024x256, z=3] -> fp32 interleaved
    mma_gemm<128, 0><<<dim3(8, 32, 3), blk, smem128>>>(
        p_xt, NF, p_wih, (size_t)G4 * HD, nullptr, p_bp, G4,
        p_gx, NG4, nullptr, nullptr, nullptr, nullptr, nullptr, nullptr, G4, HD);

    // t = 0
    lstm_init<<<(int)((KEXP * NF) / 256), 256>>>();

    // t = 1..4 : fused GEMM + gate
    __half* hbuf[2] = { p_h0, p_h1 };
    for (int t = 1; t < TSTEP; t++) {
        __half* hin  = hbuf[(t - 1) & 1];
        __half* hout = hbuf[t & 1];
        mma_gemm<128, 1><<<dim3(8, 32, 3), blk, smem128>>>(
            hin, NF, p_whh, (size_t)G4 * HD, nullptr, nullptr, 0,
            nullptr, 0, p_gx, p_c, hout, nullptr, nullptr, nullptr, G4, HD);
    }

    // fc: delta = tanh(h @ fc_w^T + fc_b); zbar fused   [NT 4096x256x256, z=3]
    mma_gemm<128, 2><<<dim3(2, 32, 3), blk, smem128>>>(
        hbuf[(TSTEP - 1) & 1], NF, p_fcw, (size_t)FD * HD, nullptr, fc_b, FD,
        nullptr, 0, nullptr, nullptr, nullptr, x, p_delta, out_zbar, FD, HD);

    final_pred<<<(int)(NF / 256), 256>>>(x, out_pred);
}